// round 16
// baseline (speedup 1.0000x reference)
#include <cuda_runtime.h>
#include <cuda_fp16.h>
#include <cstdint>

#define B_   4
#define S_   2048
#define D_   1024
#define H_   16
#define HD_  64
#define MTOT (B_ * S_)   // 8192

// ---------------------------------------------------------------------------
// Scratch (module-load device globals; allocation-free at run time)
// ---------------------------------------------------------------------------
__device__ __half g_xp [MTOT * D_];     // x + pe (fp16)
__device__ __half g_q  [MTOT * D_];     // [B,H,S,HD] (fp16, pre-scaled)
__device__ __half g_k  [MTOT * D_];
__device__ __half g_v  [MTOT * D_];
__device__ __half g_o  [MTOT * D_];     // attention out [B,S,D] (fp16)
__device__ float  g_h  [MTOT * D_];     // pre-LN hidden (fp32)
__device__ __half g_wt4[4 * D_ * D_];   // 4 transposed weights [N,K] (fp16), q|k|v|o

// ---------------------------------------------------------------------------
__device__ __forceinline__ void mma16(float c[4], const uint32_t a[4], const uint32_t b[2]) {
    asm volatile("mma.sync.aligned.m16n8k16.row.col.f32.f16.f16.f32 "
                 "{%0,%1,%2,%3}, {%4,%5,%6,%7}, {%8,%9}, {%0,%1,%2,%3};"
                 : "+f"(c[0]), "+f"(c[1]), "+f"(c[2]), "+f"(c[3])
                 : "r"(a[0]), "r"(a[1]), "r"(a[2]), "r"(a[3]), "r"(b[0]), "r"(b[1]));
}
__device__ __forceinline__ uint32_t cvta_smem(const void* p) {
    uint32_t a;
    asm("{ .reg .u64 t; cvta.to.shared.u64 t, %1; cvt.u32.u64 %0, t; }" : "=r"(a) : "l"(p));
    return a;
}
__device__ __forceinline__ void ldsm4(uint32_t r[4], uint32_t addr) {
    asm volatile("ldmatrix.sync.aligned.m8n8.x4.shared.b16 {%0,%1,%2,%3}, [%4];"
                 : "=r"(r[0]), "=r"(r[1]), "=r"(r[2]), "=r"(r[3]) : "r"(addr));
}
__device__ __forceinline__ void ldsm4t(uint32_t r[4], uint32_t addr) {
    asm volatile("ldmatrix.sync.aligned.m8n8.x4.trans.shared.b16 {%0,%1,%2,%3}, [%4];"
                 : "=r"(r[0]), "=r"(r[1]), "=r"(r[2]), "=r"(r[3]) : "r"(addr));
}
#define CP_ASYNC16(dst, src) \
    asm volatile("cp.async.cg.shared.global [%0], [%1], 16;" :: "r"(dst), "l"(src) : "memory")
#define CP_COMMIT() asm volatile("cp.async.commit_group;" ::: "memory")
#define CP_WAIT0()  asm volatile("cp.async.wait_group 0;" ::: "memory")
#define CP_WAIT1()  asm volatile("cp.async.wait_group 1;" ::: "memory")

// ---------------------------------------------------------------------------
// x + positional encoding -> g_xp (fp16)
// ---------------------------------------------------------------------------
__global__ __launch_bounds__(256) void pe_add_kernel(const float* __restrict__ x,
                                                     const float* __restrict__ pe) {
    int i = blockIdx.x * 256 + threadIdx.x;   // float4 index
    int row = i >> 8;
    int s   = row & (S_ - 1);
    int d4  = i & 255;
    float4 a = reinterpret_cast<const float4*>(x)[i];
    float4 p = reinterpret_cast<const float4*>(pe)[s * 256 + d4];
    __half2 h0 = __floats2half2_rn(a.x + p.x, a.y + p.y);
    __half2 h1 = __floats2half2_rn(a.z + p.z, a.w + p.w);
    *reinterpret_cast<__half2*>(&g_xp[i * 4])     = h0;
    *reinterpret_cast<__half2*>(&g_xp[i * 4 + 2]) = h1;
}

// ---------------------------------------------------------------------------
// Batched transpose of all 4 weights: wt4[z][n][k] = fp16(Wz[k][n])
// ---------------------------------------------------------------------------
__global__ __launch_bounds__(256) void transpose4_kernel(const float* __restrict__ w0,
                                                         const float* __restrict__ w1,
                                                         const float* __restrict__ w2,
                                                         const float* __restrict__ w3) {
    __shared__ float tile[32][33];
    const float* W = (blockIdx.z == 0) ? w0 : (blockIdx.z == 1) ? w1
                   : (blockIdx.z == 2) ? w2 : w3;
    __half* Wt = g_wt4 + (size_t)blockIdx.z * D_ * D_;
    int bx = blockIdx.x * 32, by = blockIdx.y * 32;
#pragma unroll
    for (int i = 0; i < 32; i += 8)
        tile[threadIdx.y + i][threadIdx.x] = W[(by + threadIdx.y + i) * D_ + bx + threadIdx.x];
    __syncthreads();
#pragma unroll
    for (int i = 0; i < 32; i += 8)
        Wt[(size_t)(bx + threadIdx.y + i) * D_ + by + threadIdx.x] =
            __float2half_rn(tile[threadIdx.x][threadIdx.y + i]);
}

// ---------------------------------------------------------------------------
// fp16 mma.sync GEMM (unchanged from round 14): 8 warps, CTA 128x128,
// K-chunk 64 halves, 3-stage cp.async, fused-QKV MODE 0 / out-proj MODE 1.
// ---------------------------------------------------------------------------
#define SSTRH 72
#define ABYT  (128 * SSTRH * 2)
#define BUFB  (2 * ABYT)
#define NSTAGE 3
#define GSM_TOTAL (NSTAGE * BUFB)          // 110592 B
#define NCHUNK 16

template <int MODE>
__global__ __launch_bounds__(256, 2) void gemm_mma_kernel(const __half* __restrict__ A,
                                                          const __half* __restrict__ Wt,
                                                          const float* __restrict__ b0,
                                                          const float* __restrict__ b1,
                                                          const float* __restrict__ b2,
                                                          const __half* __restrict__ resid,
                                                          void* __restrict__ out0,
                                                          void* __restrict__ out1,
                                                          void* __restrict__ out2) {
    extern __shared__ uint32_t smem[];
    const uint32_t sb = cvta_smem(smem);
    const int t    = threadIdx.x;
    const int wid  = t >> 5;
    const int lane = t & 31;
    const int grp  = lane >> 2;
    const int tg   = lane & 3;
    const int wm   = wid & 1;
    const int wn   = wid >> 1;
    const int mBase = blockIdx.y * 128;
    const int nGlob = blockIdx.x * 128;

    const int lm  = lane & 7;
    const int sel = lane >> 3;
    const int a_row_off = lm + ((sel & 1) ? 8 : 0);
    const int a_col_off = (sel & 2) ? 8 : 0;
    const int b_row_off = lm + ((sel & 2) ? 8 : 0);
    const int b_col_off = (sel & 1) ? 8 : 0;

    float acc[4][4][4];
#pragma unroll
    for (int i = 0; i < 4; i++)
#pragma unroll
        for (int j = 0; j < 4; j++)
#pragma unroll
            for (int r = 0; r < 4; r++) acc[i][j][r] = 0.f;

    auto issue = [&](int c, int buf) {
        const uint32_t base = sb + buf * BUFB;
#pragma unroll
        for (int ii = 0; ii < 4; ii++) {
            const int i   = t + 256 * ii;
            const int row = i >> 3;
            const int c8  = i & 7;
            const __half* sa = A  + (size_t)(mBase + row) * D_ + c * 64 + c8 * 8;
            const __half* sw = Wt + (size_t)(nGlob + row) * D_ + c * 64 + c8 * 8;
            CP_ASYNC16(base + 2 * (row * SSTRH + c8 * 8), sa);
            CP_ASYNC16(base + ABYT + 2 * (row * SSTRH + c8 * 8), sw);
        }
        CP_COMMIT();
    };

    auto compute = [&](int buf) {
        const uint32_t sA = sb + buf * BUFB;
        const uint32_t sB = sA + ABYT;
#pragma unroll
        for (int ks = 0; ks < 4; ks++) {
            const int kb = ks * 16;
            uint32_t af[4][4], bm[2][4];
#pragma unroll
            for (int mf = 0; mf < 4; mf++)
                ldsm4(af[mf], sA + 2 * ((wm * 64 + mf * 16 + a_row_off) * SSTRH + kb + a_col_off));
#pragma unroll
            for (int p = 0; p < 2; p++)
                ldsm4(bm[p], sB + 2 * ((wn * 32 + p * 16 + b_row_off) * SSTRH + kb + b_col_off));
#pragma unroll
            for (int mf = 0; mf < 4; mf++)
#pragma unroll
                for (int nf = 0; nf < 4; nf++) {
                    uint32_t bf[2] = { bm[nf >> 1][(nf & 1) * 2],
                                       bm[nf >> 1][(nf & 1) * 2 + 1] };
                    mma16(acc[mf][nf], af[mf], bf);
                }
        }
    };

    issue(0, 0);
    issue(1, 1);
#pragma unroll 1
    for (int c = 0; c < NCHUNK; c++) {
        if (c <= NCHUNK - 3) CP_WAIT1(); else CP_WAIT0();
        __syncthreads();
        if (c + 2 < NCHUNK) issue(c + 2, (c + 2) % 3);
        compute(c % 3);
    }

    const int z = (MODE == 0) ? (nGlob >> 10) : 0;
    const float* bias = (MODE == 0) ? ((z == 0) ? b0 : (z == 1) ? b1 : b2) : b0;
    const float scale = (MODE == 0 && z == 0) ? 0.125f : 1.0f;
    const int nIn = nGlob & 1023;

    float2 bz[4];
#pragma unroll
    for (int nf = 0; nf < 4; nf++)
        bz[nf] = *reinterpret_cast<const float2*>(bias + nIn + wn * 32 + nf * 8 + tg * 2);

#pragma unroll
    for (int mf = 0; mf < 4; mf++) {
#pragma unroll
        for (int half = 0; half < 2; half++) {
            const int gm = mBase + wm * 64 + mf * 16 + grp + half * 8;
            if (MODE == 0) {
                __half* out = (__half*)((z == 0) ? out0 : (z == 1) ? out1 : out2);
                const int h = (nIn + wn * 32) >> 6;
                const int b = gm >> 11;
                const int s = gm & (S_ - 1);
                __half* dst = out + (((size_t)(b * H_ + h)) * S_ + s) * HD_;
#pragma unroll
                for (int nf = 0; nf < 4; nf++) {
                    const int hd = (nIn + wn * 32 + nf * 8 + tg * 2) & 63;
                    *reinterpret_cast<__half2*>(dst + hd) = __floats2half2_rn(
                        (acc[mf][nf][half * 2 + 0] + bz[nf].x) * scale,
                        (acc[mf][nf][half * 2 + 1] + bz[nf].y) * scale);
                }
            } else {
                float* out = (float*)out0;
                const __half* rr = resid + (size_t)gm * D_;
                float* orow      = out   + (size_t)gm * D_;
#pragma unroll
                for (int nf = 0; nf < 4; nf++) {
                    const int n = nIn + wn * 32 + nf * 8 + tg * 2;
                    float2 r2 = __half22float2(*reinterpret_cast<const __half2*>(rr + n));
                    float2 v2;
                    v2.x = acc[mf][nf][half * 2 + 0] + bz[nf].x + r2.x;
                    v2.y = acc[mf][nf][half * 2 + 1] + bz[nf].y + r2.y;
                    *reinterpret_cast<float2*>(orow + n) = v2;
                }
            }
        }
    }
}

// ---------------------------------------------------------------------------
// Flash attention fp16: 8 warps (256 thr), 16 queries/warp, q-tile 128,
// keys 64/tile, split-phase cp.async K/V prefetch, Q frags register-resident.
// SMEM (halves): Q 128x72 | K 64x72 | V 64x72 | P 8x(16x72)
// ---------------------------------------------------------------------------
#define QSTRH 72
#define KSTRH 72
#define VSTRH 72
#define PSTRH 72
#define FQH 0
#define FKH (128 * QSTRH)
#define FVH (FKH + 64 * KSTRH)
#define FPH (FVH + 64 * VSTRH)
#define PWB (16 * PSTRH * 2)                 // per-warp P bytes (2304)
#define FSM_TOTAL ((FPH + 8 * 16 * PSTRH) * 2)   // 55296 B

__global__ __launch_bounds__(256, 2) void flash_mma_kernel(const __half* __restrict__ Qg,
                                                           const __half* __restrict__ Kg,
                                                           const __half* __restrict__ Vg,
                                                           __half* __restrict__ Og) {
    extern __shared__ __half fsm[];
    const uint32_t sb  = cvta_smem(fsm);
    const uint32_t sbQ = sb + FQH * 2;
    const uint32_t sbK = sb + FKH * 2;
    const uint32_t sbV = sb + FVH * 2;
    const uint32_t sbP = sb + FPH * 2;
    __half* Psm = fsm + FPH;

    const int t    = threadIdx.x;
    const int wid  = t >> 5;      // 0..7
    const int lane = t & 31;
    const int grp  = lane >> 2;
    const int tg   = lane & 3;
    const int bh   = blockIdx.y;
    const int qb   = blockIdx.x * 128;

    const int lm  = lane & 7;
    const int sel = lane >> 3;
    const int a_row_off = lm + ((sel & 1) ? 8 : 0);
    const int a_col_off = (sel & 2) ? 8 : 0;
    const int b_row_off = lm + ((sel & 2) ? 8 : 0);
    const int b_col_off = (sel & 1) ? 8 : 0;
    const int v_row_off = lm + ((sel & 1) ? 8 : 0);
    const int v_col_off = (sel & 2) ? 8 : 0;

    const __half* Qh = Qg + (size_t)bh * S_ * HD_;
    const __half* Kh = Kg + (size_t)bh * S_ * HD_;
    const __half* Vh = Vg + (size_t)bh * S_ * HD_;

    auto issueK = [&](int kt) {
#pragma unroll
        for (int ii = 0; ii < 2; ii++) {
            const int i   = t + 256 * ii;   // 0..511
            const int row = i >> 3;         // 0..63
            const int c8  = i & 7;
            CP_ASYNC16(sbK + 2 * (row * KSTRH + c8 * 8),
                       Kh + (size_t)(kt + row) * HD_ + c8 * 8);
        }
        CP_COMMIT();
    };
    auto issueV = [&](int kt) {
#pragma unroll
        for (int ii = 0; ii < 2; ii++) {
            const int i   = t + 256 * ii;
            const int row = i >> 3;
            const int c8  = i & 7;
            CP_ASYNC16(sbV + 2 * (row * VSTRH + c8 * 8),
                       Vh + (size_t)(kt + row) * HD_ + c8 * 8);
        }
        CP_COMMIT();
    };

    // Q (group 1), K0 (group 2), V0 (group 3)
#pragma unroll
    for (int ii = 0; ii < 4; ii++) {
        const int i   = t + 256 * ii;       // 0..1023
        const int row = i >> 3;             // 0..127
        const int c8  = i & 7;
        CP_ASYNC16(sbQ + 2 * (row * QSTRH + c8 * 8),
                   Qh + (size_t)(qb + row) * HD_ + c8 * 8);
    }
    CP_COMMIT();
    issueK(0);
    issueV(0);

    __half* Pw = Psm + wid * 16 * PSTRH;
    const uint32_t Pw_sb = sbP + wid * PWB;

    uint32_t qf[4][4];               // register-resident Q frags (loaded at n==0)
    float m0 = -1e30f, m1 = -1e30f, l0 = 0.f, l1 = 0.f;
    float o[8][4];
#pragma unroll
    for (int nt = 0; nt < 8; nt++)
#pragma unroll
        for (int r = 0; r < 4; r++) o[nt][r] = 0.f;

#pragma unroll 1
    for (int n = 0; n < 32; n++) {
        const int kt = n * 64;
        CP_WAIT1();                  // Q(+K at n=0) / K(n) complete
        __syncthreads();

        if (n == 0) {
#pragma unroll
            for (int s = 0; s < 4; s++)
                ldsm4(qf[s], sbQ + 2 * ((wid * 16 + a_row_off) * QSTRH + s * 16 + a_col_off));
        }

        // ---- scores = Q @ K^T ----
        float sc[8][4];
#pragma unroll
        for (int nt = 0; nt < 8; nt++)
#pragma unroll
            for (int r = 0; r < 4; r++) sc[nt][r] = 0.f;
#pragma unroll
        for (int s = 0; s < 4; s++) {
            const int kb = s * 16;
            uint32_t bm[4][4];
#pragma unroll
            for (int p = 0; p < 4; p++)
                ldsm4(bm[p], sbK + 2 * ((p * 16 + b_row_off) * KSTRH + kb + b_col_off));
#pragma unroll
            for (int nt = 0; nt < 8; nt++) {
                uint32_t bf[2] = { bm[nt >> 1][(nt & 1) * 2],
                                   bm[nt >> 1][(nt & 1) * 2 + 1] };
                mma16(sc[nt], qf[s], bf);
            }
        }

        __syncthreads();
        if (n + 1 < 32) issueK(kt + 64);

        // ---- online softmax (rows grp, grp+8) ----
        float mx0 = -1e30f, mx1 = -1e30f;
#pragma unroll
        for (int nt = 0; nt < 8; nt++) {
            mx0 = fmaxf(mx0, fmaxf(sc[nt][0], sc[nt][1]));
            mx1 = fmaxf(mx1, fmaxf(sc[nt][2], sc[nt][3]));
        }
        mx0 = fmaxf(mx0, __shfl_xor_sync(0xffffffffu, mx0, 1));
        mx0 = fmaxf(mx0, __shfl_xor_sync(0xffffffffu, mx0, 2));
        mx1 = fmaxf(mx1, __shfl_xor_sync(0xffffffffu, mx1, 1));
        mx1 = fmaxf(mx1, __shfl_xor_sync(0xffffffffu, mx1, 2));
        const float mn0 = fmaxf(m0, mx0);
        const float mn1 = fmaxf(m1, mx1);
        const float a0 = __expf(m0 - mn0);
        const float a1 = __expf(m1 - mn1);
        m0 = mn0; m1 = mn1;
        float s0 = 0.f, s1 = 0.f;
#pragma unroll
        for (int nt = 0; nt < 8; nt++) {
            sc[nt][0] = __expf(sc[nt][0] - mn0);
            sc[nt][1] = __expf(sc[nt][1] - mn0);
            sc[nt][2] = __expf(sc[nt][2] - mn1);
            sc[nt][3] = __expf(sc[nt][3] - mn1);
            s0 += sc[nt][0] + sc[nt][1];
            s1 += sc[nt][2] + sc[nt][3];
        }
        s0 += __shfl_xor_sync(0xffffffffu, s0, 1);
        s0 += __shfl_xor_sync(0xffffffffu, s0, 2);
        s1 += __shfl_xor_sync(0xffffffffu, s1, 1);
        s1 += __shfl_xor_sync(0xffffffffu, s1, 2);
        l0 = l0 * a0 + s0;
        l1 = l1 * a1 + s1;
#pragma unroll
        for (int nt = 0; nt < 8; nt++) {
            o[nt][0] *= a0; o[nt][1] *= a0;
            o[nt][2] *= a1; o[nt][3] *= a1;
        }
        // store P (fp16): rows grp / grp+8 of this warp's 16-row region
#pragma unroll
        for (int nt = 0; nt < 8; nt++) {
            *reinterpret_cast<__half2*>(&Pw[grp * PSTRH + nt * 8 + tg * 2]) =
                __floats2half2_rn(sc[nt][0], sc[nt][1]);
            *reinterpret_cast<__half2*>(&Pw[(grp + 8) * PSTRH + nt * 8 + tg * 2]) =
                __floats2half2_rn(sc[nt][2], sc[nt][3]);
        }
        __syncwarp();

        if (n + 1 < 32) CP_WAIT1(); else CP_WAIT0();   // V(n) complete
        __syncthreads();

        // ---- O += P @ V ----
#pragma unroll
        for (int s = 0; s < 4; s++) {
            const int kb = s * 16;
            uint32_t pf[4], bm[4][4];
            ldsm4(pf, Pw_sb + 2 * (a_row_off * PSTRH + kb + a_col_off));
#pragma unroll
            for (int p = 0; p < 4; p++)
                ldsm4t(bm[p], sbV + 2 * ((kb + v_row_off) * VSTRH + p * 16 + v_col_off));
#pragma unroll
            for (int nt = 0; nt < 8; nt++) {
                uint32_t bf[2] = { bm[nt >> 1][(nt & 1) * 2],
                                   bm[nt >> 1][(nt & 1) * 2 + 1] };
                mma16(o[nt], pf, bf);
            }
        }

        __syncthreads();
        if (n + 1 < 32) issueV(kt + 64);
    }

    // ---- epilogue: O/l -> g_o (fp16, [B,S,D]) ----
    const int b = bh >> 4, h = bh & 15;
    const float inv0 = 1.0f / l0;
    const float inv1 = 1.0f / l1;
    const int r0 = qb + wid * 16 + grp;
    __half* base0 = Og + ((size_t)b * S_ + r0) * D_ + h * HD_;
    __half* base1 = base0 + (size_t)8 * D_;
#pragma unroll
    for (int nt = 0; nt < 8; nt++) {
        *reinterpret_cast<__half2*>(base0 + nt * 8 + tg * 2) =
            __floats2half2_rn(o[nt][0] * inv0, o[nt][1] * inv0);
        *reinterpret_cast<__half2*>(base1 + nt * 8 + tg * 2) =
            __floats2half2_rn(o[nt][2] * inv1, o[nt][3] * inv1);
    }
}

// ---------------------------------------------------------------------------
// LayerNorm over last dim (1024), one block per row
// ---------------------------------------------------------------------------
__global__ __launch_bounds__(256) void ln_kernel(const float* __restrict__ Hm,
                                                 const float* __restrict__ gamma,
                                                 const float* __restrict__ beta,
                                                 float* __restrict__ out) {
    const int row = blockIdx.x;
    const int t   = threadIdx.x;
    const float* hr = Hm + (size_t)row * D_;
    float4 v = *reinterpret_cast<const float4*>(hr + t * 4);
    float s  = v.x + v.y + v.z + v.w;
    float ss = v.x * v.x + v.y * v.y + v.z * v.z + v.w * v.w;
#pragma unroll
    for (int msk = 16; msk > 0; msk >>= 1) {
        s  += __shfl_xor_sync(0xffffffffu, s, msk);
        ss += __shfl_xor_sync(0xffffffffu, ss, msk);
    }
    __shared__ float rs[8], rss[8];
    __shared__ float mu_s, rstd_s;
    int w = t >> 5;
    if ((t & 31) == 0) { rs[w] = s; rss[w] = ss; }
    __syncthreads();
    if (t == 0) {
        float S = 0.f, SS = 0.f;
#pragma unroll
        for (int i = 0; i < 8; i++) { S += rs[i]; SS += rss[i]; }
        float mu  = S * (1.0f / D_);
        float var = SS * (1.0f / D_) - mu * mu;
        mu_s = mu;
        rstd_s = rsqrtf(var + 1e-5f);
    }
    __syncthreads();
    float mu = mu_s, rstd = rstd_s;
    float4 g4 = *reinterpret_cast<const float4*>(gamma + t * 4);
    float4 b4 = *reinterpret_cast<const float4*>(beta + t * 4);
    float4 o4;
    o4.x = (v.x - mu) * rstd * g4.x + b4.x;
    o4.y = (v.y - mu) * rstd * g4.y + b4.y;
    o4.z = (v.z - mu) * rstd * g4.z + b4.z;
    o4.w = (v.w - mu) * rstd * g4.w + b4.w;
    *reinterpret_cast<float4*>(out + (size_t)row * D_ + t * 4) = o4;
}

// ---------------------------------------------------------------------------
extern "C" void kernel_launch(void* const* d_in, const int* in_sizes, int n_in,
                              void* d_out, int out_size) {
    (void)in_sizes; (void)n_in; (void)out_size;
    const float* x     = (const float*)d_in[0];
    const float* wq    = (const float*)d_in[1];
    const float* bq    = (const float*)d_in[2];
    const float* wk    = (const float*)d_in[3];
    const float* bk    = (const float*)d_in[4];
    const float* wv    = (const float*)d_in[5];
    const float* bv    = (const float*)d_in[6];
    const float* wo    = (const float*)d_in[7];
    const float* bo    = (const float*)d_in[8];
    const float* gamma = (const float*)d_in[9];
    const float* beta  = (const float*)d_in[10];
    const float* pe    = (const float*)d_in[11];
    float* out = (float*)d_out;

    __half *xp, *q, *k, *v, *o, *wt;
    float *h;
    cudaGetSymbolAddress((void**)&xp, g_xp);
    cudaGetSymbolAddress((void**)&q,  g_q);
    cudaGetSymbolAddress((void**)&k,  g_k);
    cudaGetSymbolAddress((void**)&v,  g_v);
    cudaGetSymbolAddress((void**)&o,  g_o);
    cudaGetSymbolAddress((void**)&h,  g_h);
    cudaGetSymbolAddress((void**)&wt, g_wt4);

    cudaFuncSetAttribute(gemm_mma_kernel<0>,
                         cudaFuncAttributeMaxDynamicSharedMemorySize, GSM_TOTAL);
    cudaFuncSetAttribute(gemm_mma_kernel<1>,
                         cudaFuncAttributeMaxDynamicSharedMemorySize, GSM_TOTAL);
    cudaFuncSetAttribute(flash_mma_kernel,
                         cudaFuncAttributeMaxDynamicSharedMemorySize, FSM_TOTAL);

    // 1) x + pe (fp16)
    pe_add_kernel<<<(MTOT * D_ / 4) / 256, 256>>>(x, pe);

    // 2) transpose + convert all 4 weights -> g_wt4 [N,K] fp16 (q|k|v|o contiguous)
    transpose4_kernel<<<dim3(32, 32, 4), dim3(32, 8)>>>(wq, wk, wv, wo);

    // 3) fused Q/K/V projection: N = 3072 in one launch
    dim3 qkvgrid(3 * D_ / 128, MTOT / 128);
    gemm_mma_kernel<0><<<qkvgrid, 256, GSM_TOTAL>>>(xp, wt, bq, bk, bv, nullptr,
                                                    q, k, v);

    // 4) attention (256 threads / 8 warps per CTA)
    dim3 fgrid(S_ / 128, B_ * H_);
    flash_mma_kernel<<<fgrid, 256, FSM_TOTAL>>>(q, k, v, o);

    // 5) output projection + bias + residual (fp32 out)
    dim3 ogrid(D_ / 128, MTOT / 128);
    gemm_mma_kernel<1><<<ogrid, 256, GSM_TOTAL>>>(o, wt + 3 * (size_t)D_ * D_, bo,
                                                  nullptr, nullptr, xp, h, nullptr, nullptr);

    // 6) layernorm
    ln_kernel<<<MTOT, 256>>>(h, gamma, beta, out);
}